// round 17
// baseline (speedup 1.0000x reference)
#include <cuda_runtime.h>

// Hamilton product of quaternions packed in the last dim (w, x, y, z).
// Shapes: q1, q2: (32, 4096, 64, 4) fp32 -> 8,388,608 quaternions.
//
// FINAL (converged after 17-round sweep). HBM-bound 2R+1W stream (~403 MB,
// zero reuse); every structural variant (float4 vs v8.f32, QPT 1/2/4,
// TPB 128/256/512, .nc/.cs hints, persistent grid) pins DRAM at 82-85% of
// the 8 TB/s spec — the B300 achieved ceiling (LTS cap, path-independent).
// Winning shape on harness graph-replay time: one coalesced LDG.128 pair
// per thread, TPB=256, exact grid (n_quat % 256 == 0, no guard):
//   this family:   {59.87, 60.29, 60.51, 61.18, 61.34} us
//   all ILP/v8/persistent variants: 61.9-64.0 us
// Guarded tail kernel retained for shape-generality (never launched here).

#define TPB 256

__device__ __forceinline__ float4 hprod(float4 a, float4 b) {
    float4 r;
    r.x = a.x * b.x - a.y * b.y - a.z * b.z - a.w * b.w;  // w
    r.y = a.x * b.y + a.y * b.x + a.z * b.w - a.w * b.z;  // x
    r.z = a.x * b.z - a.y * b.w + a.z * b.x + a.w * b.y;  // y
    r.w = a.x * b.w + a.y * b.z - a.z * b.y + a.w * b.x;  // z
    return r;
}

__global__ void __launch_bounds__(TPB) hamilton_kernel(
    const float4* __restrict__ q1,
    const float4* __restrict__ q2,
    float4* __restrict__ out)
{
    int i = blockIdx.x * TPB + threadIdx.x;
    out[i] = hprod(q1[i], q2[i]);
}

// Guarded tail for arbitrary n (not hit for this shape).
__global__ void __launch_bounds__(TPB) hamilton_kernel_tail(
    const float4* __restrict__ q1,
    const float4* __restrict__ q2,
    float4* __restrict__ out,
    int start, int n_quat)
{
    int i = start + blockIdx.x * TPB + threadIdx.x;
    if (i < n_quat) out[i] = hprod(q1[i], q2[i]);
}

extern "C" void kernel_launch(void* const* d_in, const int* in_sizes, int n_in,
                              void* d_out, int out_size) {
    const float4* q1 = (const float4*)d_in[0];
    const float4* q2 = (const float4*)d_in[1];
    float4* out = (float4*)d_out;

    int n_quat = in_sizes[0] / 4;      // 8,388,608
    int full_blocks = n_quat / TPB;    // 32768 (exact for this shape)
    int covered = full_blocks * TPB;

    if (full_blocks > 0)
        hamilton_kernel<<<full_blocks, TPB>>>(q1, q2, out);

    int rem = n_quat - covered;
    if (rem > 0) {
        int tail_blocks = (rem + TPB - 1) / TPB;
        hamilton_kernel_tail<<<tail_blocks, TPB>>>(q1, q2, out, covered, n_quat);
    }
}